// round 5
// baseline (speedup 1.0000x reference)
#include <cuda_runtime.h>
#include <math.h>
#include <stdint.h>

// ---------------- problem constants ----------------
#define D_MODEL 1024
#define D_FF    4096
#define NH      16
#define DKV     64
#define SEQ     2048
#define BATCH   2
#define ROWS    (BATCH*SEQ)        // 4096
#define RELN    (2*SEQ-1)          // 4095

// ---------------- scratch (device globals, no allocation) ----------------
__device__ float g_normed [ROWS*D_MODEL];
__device__ float g_q      [ROWS*D_MODEL];
__device__ float g_k      [ROWS*D_MODEL];
__device__ float g_v      [ROWS*D_MODEL];
__device__ float g_ctx    [ROWS*D_MODEL];
__device__ float g_hidden2[ROWS*D_MODEL];
__device__ float g_normed2[ROWS*D_MODEL];
__device__ float g_ff1    [ROWS*D_FF];
__device__ float g_ff2    [ROWS*D_FF];
__device__ float g_biasRel[NH*RELN];

// ---------------- T5 relative-position bias table ----------------
// biasRel[h][rel + (S-1)] = rel_bias[bucket(rel)][h],  rel = k - q
__global__ void bias_kernel(const float* __restrict__ rel_bias,
                            float* __restrict__ biasRel) {
    int idx = blockIdx.x * 256 + threadIdx.x;
    if (idx >= NH * RELN) return;
    int h   = idx / RELN;
    int r   = idx % RELN;
    int rel = r - (SEQ - 1);
    int ret = (rel > 0) ? 16 : 0;          // num_buckets/2
    int n   = rel < 0 ? -rel : rel;
    int v;
    if (n < 8) {                            // max_exact = 8
        v = n;
    } else {
        // double precision so exact crossings (n = 16,32,64) truncate correctly
        double t = log((double)n / 8.0) / log(16.0) * 8.0;
        v = 8 + (int)t;
        if (v > 15) v = 15;
    }
    biasRel[idx] = rel_bias[(ret + v) * NH + h];
}

// ---------------- RMSNorm: one block per row, 256 threads ----------------
__global__ __launch_bounds__(256) void rmsnorm_kernel(
    const float* __restrict__ x, const float* __restrict__ w,
    float* __restrict__ out) {
    int row = blockIdx.x;
    int t   = threadIdx.x;
    const float4* xr = reinterpret_cast<const float4*>(x + (size_t)row * D_MODEL);
    float4 v = xr[t];
    float ss = v.x*v.x + v.y*v.y + v.z*v.z + v.w*v.w;
    #pragma unroll
    for (int o = 16; o > 0; o >>= 1) ss += __shfl_xor_sync(0xffffffffu, ss, o);
    __shared__ float ws[8];
    if ((t & 31) == 0) ws[t >> 5] = ss;
    __syncthreads();
    float tot = 0.f;
    #pragma unroll
    for (int i = 0; i < 8; i++) tot += ws[i];
    float r = rsqrtf(tot * (1.0f / D_MODEL) + 1e-6f);
    const float4* wr = reinterpret_cast<const float4*>(w);
    float4 wv = wr[t];
    float4 o4 = make_float4(v.x*r*wv.x, v.y*r*wv.y, v.z*r*wv.z, v.w*r*wv.w);
    reinterpret_cast<float4*>(out + (size_t)row * D_MODEL)[t] = o4;
}

// ---------------- SGEMM: C = A[MxK] @ B[KxN] (+ Res), 128x128x8 tiles ----------------
__global__ __launch_bounds__(256) void sgemm_kernel(
    const float* __restrict__ A, const float* __restrict__ B,
    float* __restrict__ C, const float* __restrict__ Res,
    int M, int N, int K) {
    __shared__ float As[8][128];
    __shared__ float Bs[8][128];
    int tid = threadIdx.x;
    int bx = blockIdx.x, by = blockIdx.y;
    int arow = tid >> 1;
    int acol = (tid & 1) << 2;
    int brow = tid >> 5;
    int bcol = (tid & 31) << 2;
    int tx = tid & 15, ty = tid >> 4;
    const float* Ap = A + (size_t)(by * 128 + arow) * K + acol;
    const float* Bp = B + (size_t)brow * N + bx * 128 + bcol;
    float acc[8][8];
    #pragma unroll
    for (int i = 0; i < 8; i++)
        #pragma unroll
        for (int j = 0; j < 8; j++) acc[i][j] = 0.f;

    for (int k0 = 0; k0 < K; k0 += 8) {
        float4 av = *reinterpret_cast<const float4*>(Ap + k0);
        float4 bv = *reinterpret_cast<const float4*>(Bp + (size_t)k0 * N);
        As[acol + 0][arow] = av.x;
        As[acol + 1][arow] = av.y;
        As[acol + 2][arow] = av.z;
        As[acol + 3][arow] = av.w;
        *reinterpret_cast<float4*>(&Bs[brow][bcol]) = bv;
        __syncthreads();
        #pragma unroll
        for (int kk = 0; kk < 8; kk++) {
            float4 a0 = *reinterpret_cast<const float4*>(&As[kk][ty * 8]);
            float4 a1 = *reinterpret_cast<const float4*>(&As[kk][ty * 8 + 4]);
            float4 b0 = *reinterpret_cast<const float4*>(&Bs[kk][tx * 8]);
            float4 b1 = *reinterpret_cast<const float4*>(&Bs[kk][tx * 8 + 4]);
            float a[8] = {a0.x,a0.y,a0.z,a0.w,a1.x,a1.y,a1.z,a1.w};
            float b[8] = {b0.x,b0.y,b0.z,b0.w,b1.x,b1.y,b1.z,b1.w};
            #pragma unroll
            for (int i = 0; i < 8; i++)
                #pragma unroll
                for (int j = 0; j < 8; j++)
                    acc[i][j] = fmaf(a[i], b[j], acc[i][j]);
        }
        __syncthreads();
    }
    #pragma unroll
    for (int i = 0; i < 8; i++) {
        int row = by * 128 + ty * 8 + i;
        float* Cp = C + (size_t)row * N + bx * 128 + tx * 8;
        if (Res) {
            const float* Rp = Res + (size_t)row * N + bx * 128 + tx * 8;
            #pragma unroll
            for (int j = 0; j < 8; j++) Cp[j] = acc[i][j] + Rp[j];
        } else {
            #pragma unroll
            for (int j = 0; j < 8; j++) Cp[j] = acc[i][j];
        }
    }
}

// ---------------- Flash attention (fp32, online softmax) ----------------
// grid (S/64, H, B), 256 threads. Tiles: Q 64x64, stream K/V in 64-row tiles.
// Smem: Qt[d][m] stride 65 (transposed), Kt[d][c] stride 65 (transposed, reused
// as P[m][c] stride 65), Vs[c][d] stride 64.
#define ATTN_SMEM_FLOATS (64*65 + 64*65 + 64*64 + 128 + 64)

__global__ __launch_bounds__(256) void attn_kernel(
    const float* __restrict__ q, const float* __restrict__ k,
    const float* __restrict__ v, const float* __restrict__ biasRel,
    const float* __restrict__ amask, float* __restrict__ ctx) {
    extern __shared__ float sm[];
    float* Qt    = sm;                    // [64][65], Qt[d*65 + m]
    float* Kt    = Qt + 64 * 65;          // [64][65], Kt[d*65 + c] ; later P[m*65+c]
    float* Vs    = Kt + 64 * 65;          // [64][64], Vs[c*64 + d]
    float* biasT = Vs + 64 * 64;          // 127 used
    float* maskT = biasT + 128;           // 64

    int tid = threadIdx.x;
    int tx = tid & 15, ty = tid >> 4;
    int qb = blockIdx.x << 6;
    int h  = blockIdx.y;
    int b  = blockIdx.z;

    const float* qg = q + (size_t)(b * SEQ) * D_MODEL + h * DKV;
    const float* kg = k + (size_t)(b * SEQ) * D_MODEL + h * DKV;
    const float* vg = v + (size_t)(b * SEQ) * D_MODEL + h * DKV;

    // load Q tile (coalesced), store transposed
    for (int it = tid; it < 1024; it += 256) {
        int m  = it >> 4;
        int d4 = (it & 15) << 2;
        float4 qv = *reinterpret_cast<const float4*>(
            qg + (size_t)(qb + m) * D_MODEL + d4);
        Qt[(d4 + 0) * 65 + m] = qv.x;
        Qt[(d4 + 1) * 65 + m] = qv.y;
        Qt[(d4 + 2) * 65 + m] = qv.z;
        Qt[(d4 + 3) * 65 + m] = qv.w;
    }

    float mI[4], lI[4], o[4][4];
    #pragma unroll
    for (int i = 0; i < 4; i++) {
        mI[i] = -1e30f; lI[i] = 0.f;
        #pragma unroll
        for (int j = 0; j < 4; j++) o[i][j] = 0.f;
    }

    int ty4 = ty * 4, tx4 = tx * 4;

    for (int jb = 0; jb < SEQ; jb += 64) {
        // load K (transposed) and V tiles, bias diag slice, mask slice
        for (int it = tid; it < 1024; it += 256) {
            int c  = it >> 4;
            int d4 = (it & 15) << 2;
            float4 kv = *reinterpret_cast<const float4*>(
                kg + (size_t)(jb + c) * D_MODEL + d4);
            Kt[(d4 + 0) * 65 + c] = kv.x;
            Kt[(d4 + 1) * 65 + c] = kv.y;
            Kt[(d4 + 2) * 65 + c] = kv.z;
            Kt[(d4 + 3) * 65 + c] = kv.w;
            float4 vv = *reinterpret_cast<const float4*>(
                vg + (size_t)(jb + c) * D_MODEL + d4);
            *reinterpret_cast<float4*>(&Vs[c * 64 + d4]) = vv;
        }
        if (tid < 127)
            biasT[tid] = biasRel[h * RELN + (jb - qb + 1984 + tid)];
        if (tid >= 128 && tid < 192) {
            int c = tid - 128;
            maskT[c] = (1.0f - amask[b * SEQ + jb + c]) * -10000.0f;
        }
        __syncthreads();

        // S = Q K^T  (64x64x64)
        float sacc[4][4];
        #pragma unroll
        for (int i = 0; i < 4; i++)
            #pragma unroll
            for (int j = 0; j < 4; j++) sacc[i][j] = 0.f;
        #pragma unroll 8
        for (int d = 0; d < 64; d++) {
            float a0 = Qt[d * 65 + ty4 + 0];
            float a1 = Qt[d * 65 + ty4 + 1];
            float a2 = Qt[d * 65 + ty4 + 2];
            float a3 = Qt[d * 65 + ty4 + 3];
            float b0 = Kt[d * 65 + tx4 + 0];
            float b1 = Kt[d * 65 + tx4 + 1];
            float b2 = Kt[d * 65 + tx4 + 2];
            float b3 = Kt[d * 65 + tx4 + 3];
            sacc[0][0] = fmaf(a0,b0,sacc[0][0]); sacc[0][1] = fmaf(a0,b1,sacc[0][1]);
            sacc[0][2] = fmaf(a0,b2,sacc[0][2]); sacc[0][3] = fmaf(a0,b3,sacc[0][3]);
            sacc[1][0] = fmaf(a1,b0,sacc[1][0]); sacc[1][1] = fmaf(a1,b1,sacc[1][1]);
            sacc[1][2] = fmaf(a1,b2,sacc[1][2]); sacc[1][3] = fmaf(a1,b3,sacc[1][3]);
            sacc[2][0] = fmaf(a2,b0,sacc[2][0]); sacc[2][1] = fmaf(a2,b1,sacc[2][1]);
            sacc[2][2] = fmaf(a2,b2,sacc[2][2]); sacc[2][3] = fmaf(a2,b3,sacc[2][3]);
            sacc[3][0] = fmaf(a3,b0,sacc[3][0]); sacc[3][1] = fmaf(a3,b1,sacc[3][1]);
            sacc[3][2] = fmaf(a3,b2,sacc[3][2]); sacc[3][3] = fmaf(a3,b3,sacc[3][3]);
        }

        // bias + mask, online softmax update (16 threads per row share state)
        int bbase = tx4 - ty4 + 63;
        #pragma unroll
        for (int i = 0; i < 4; i++) {
            #pragma unroll
            for (int j = 0; j < 4; j++)
                sacc[i][j] += biasT[bbase + j - i] + maskT[tx4 + j];
            float rm = fmaxf(fmaxf(sacc[i][0], sacc[i][1]),
                             fmaxf(sacc[i][2], sacc[i][3]));
            #pragma unroll
            for (int off = 8; off > 0; off >>= 1)
                rm = fmaxf(rm, __shfl_xor_sync(0xffffffffu, rm, off));
            float mn = fmaxf(mI[i], rm);
            float alpha = expf(mI[i] - mn);
            float rs = 0.f;
            #pragma unroll
            for (int j = 0; j < 4; j++) {
                sacc[i][j] = expf(sacc[i][j] - mn);   // now P
                rs += sacc[i][j];
            }
            #pragma unroll
            for (int off = 8; off > 0; off >>= 1)
                rs += __shfl_xor_sync(0xffffffffu, rs, off);
            lI[i] = lI[i] * alpha + rs;
            mI[i] = mn;
            #pragma unroll
            for (int j = 0; j < 4; j++) o[i][j] *= alpha;
        }
        __syncthreads();   // all reads of Kt done before overwriting with P

        float* Ps = Kt;    // reuse K region as P[m][c], stride 65
        #pragma unroll
        for (int i = 0; i < 4; i++)
            #pragma unroll
            for (int j = 0; j < 4; j++)
                Ps[(ty4 + i) * 65 + tx4 + j] = sacc[i][j];
        __syncthreads();

        // O += P V  (64x64x64)
        #pragma unroll 4
        for (int c = 0; c < 64; c++) {
            float p0 = Ps[(ty4 + 0) * 65 + c];
            float p1 = Ps[(ty4 + 1) * 65 + c];
            float p2 = Ps[(ty4 + 2) * 65 + c];
            float p3 = Ps[(ty4 + 3) * 65 + c];
            float4 vv = *reinterpret_cast<const float4*>(&Vs[c * 64 + tx4]);
            o[0][0] = fmaf(p0,vv.x,o[0][0]); o[0][1] = fmaf(p0,vv.y,o[0][1]);
            o[0][2] = fmaf(p0,vv.z,o[0][2]); o[0][3] = fmaf(p0,vv.w,o[0][3]);
            o[1][0] = fmaf(p1,vv.x,o[1][0]); o[1][1] = fmaf(p1,vv.y,o[1][1]);
            o[1][2] = fmaf(p1,vv.z,o[1][2]); o[1][3] = fmaf(p1,vv.w,o[1][3]);
            o[2][0] = fmaf(p2,vv.x,o[2][0]); o[2][1] = fmaf(p2,vv.y,o[2][1]);
            o[2][2] = fmaf(p2,vv.z,o[2][2]); o[2][3] = fmaf(p2,vv.w,o[2][3]);
            o[3][0] = fmaf(p3,vv.x,o[3][0]); o[3][1] = fmaf(p3,vv.y,o[3][1]);
            o[3][2] = fmaf(p3,vv.z,o[3][2]); o[3][3] = fmaf(p3,vv.w,o[3][3]);
        }
        __syncthreads();
    }

    // normalize and write ctx[b, s, h*64+d]
    #pragma unroll
    for (int i = 0; i < 4; i++) {
        float inv = 1.0f / lI[i];
        int row = qb + ty4 + i;
        float4 ov = make_float4(o[i][0]*inv, o[i][1]*inv, o[i][2]*inv, o[i][3]*inv);
        *reinterpret_cast<float4*>(
            ctx + (size_t)(b * SEQ + row) * D_MODEL + h * DKV + tx4) = ov;
    }
}

// ---------------- gelu_new(ff1) * ff2 -> ff1 (vectorized) ----------------
__global__ void gelu_mul_kernel(float4* __restrict__ a,
                                const float4* __restrict__ bsrc, int n4) {
    int i = blockIdx.x * 256 + threadIdx.x;
    if (i >= n4) return;
    const float C = 0.7978845608028654f;   // sqrt(2/pi)
    float4 x = a[i];
    float4 g = bsrc[i];
    float4 r;
    r.x = 0.5f * x.x * (1.0f + tanhf(C * (x.x + 0.044715f * x.x * x.x * x.x))) * g.x;
    r.y = 0.5f * x.y * (1.0f + tanhf(C * (x.y + 0.044715f * x.y * x.y * x.y))) * g.y;
    r.z = 0.5f * x.z * (1.0f + tanhf(C * (x.z + 0.044715f * x.z * x.z * x.z))) * g.z;
    r.w = 0.5f * x.w * (1.0f + tanhf(C * (x.w + 0.044715f * x.w * x.w * x.w))) * g.w;
    a[i] = r;
}

// ---------------- launch ----------------
extern "C" void kernel_launch(void* const* d_in, const int* in_sizes, int n_in,
                              void* d_out, int out_size) {
    (void)in_sizes; (void)n_in; (void)out_size;
    const float* hidden = (const float*)d_in[0];
    const float* amask  = (const float*)d_in[1];
    const float* ln1    = (const float*)d_in[2];
    const float* wq     = (const float*)d_in[3];
    const float* wk     = (const float*)d_in[4];
    const float* wv     = (const float*)d_in[5];
    const float* relb   = (const float*)d_in[6];
    const float* wo     = (const float*)d_in[7];
    const float* ln2    = (const float*)d_in[8];
    const float* w1     = (const float*)d_in[9];
    const float* w2     = (const float*)d_in[10];
    const float* wout   = (const float*)d_in[11];
    float* out = (float*)d_out;

    float *normed, *qb, *kb, *vb, *ctx, *hidden2, *normed2, *ff1, *ff2, *biasRel;
    cudaGetSymbolAddress((void**)&normed,  g_normed);
    cudaGetSymbolAddress((void**)&qb,      g_q);
    cudaGetSymbolAddress((void**)&kb,      g_k);
    cudaGetSymbolAddress((void**)&vb,      g_v);
    cudaGetSymbolAddress((void**)&ctx,     g_ctx);
    cudaGetSymbolAddress((void**)&hidden2, g_hidden2);
    cudaGetSymbolAddress((void**)&normed2, g_normed2);
    cudaGetSymbolAddress((void**)&ff1,     g_ff1);
    cudaGetSymbolAddress((void**)&ff2,     g_ff2);
    cudaGetSymbolAddress((void**)&biasRel, g_biasRel);

    const int attn_smem = ATTN_SMEM_FLOATS * (int)sizeof(float);
    cudaFuncSetAttribute(attn_kernel,
                         cudaFuncAttributeMaxDynamicSharedMemorySize, attn_smem);

    // 0) relative-position bias table
    bias_kernel<<<(NH * RELN + 255) / 256, 256>>>(relb, biasRel);
    // 1) pre-LN 1
    rmsnorm_kernel<<<ROWS, 256>>>(hidden, ln1, normed);
    // 2) QKV projections
    dim3 g1(D_MODEL / 128, ROWS / 128);
    sgemm_kernel<<<g1, 256>>>(normed, wq, qb, nullptr, ROWS, D_MODEL, D_MODEL);
    sgemm_kernel<<<g1, 256>>>(normed, wk, kb, nullptr, ROWS, D_MODEL, D_MODEL);
    sgemm_kernel<<<g1, 256>>>(normed, wv, vb, nullptr, ROWS, D_MODEL, D_MODEL);
    // 3) attention
    dim3 ga(SEQ / 64, NH, BATCH);
    attn_kernel<<<ga, 256, attn_smem>>>(qb, kb, vb, biasRel, amask, ctx);
    // 4) output projection + residual
    sgemm_kernel<<<g1, 256>>>(ctx, wo, hidden2, hidden, ROWS, D_MODEL, D_MODEL);
    // 5) pre-LN 2
    rmsnorm_kernel<<<ROWS, 256>>>(hidden2, ln2, normed2);
    // 6) gated FFN
    dim3 g2(D_FF / 128, ROWS / 128);
    sgemm_kernel<<<g2, 256>>>(normed2, w1, ff1, nullptr, ROWS, D_FF, D_MODEL);
    sgemm_kernel<<<g2, 256>>>(normed2, w2, ff2, nullptr, ROWS, D_FF, D_MODEL);
    int n4 = ROWS * D_FF / 4;
    gelu_mul_kernel<<<(n4 + 255) / 256, 256>>>((float4*)ff1, (const float4*)ff2, n4);
    // 7) FFN output projection + residual -> d_out
    sgemm_kernel<<<g1, 256>>>(ff1, wout, out, hidden2, ROWS, D_MODEL, D_FF);
}

// round 6
// speedup vs baseline: 1.6442x; 1.6442x over previous
#include <cuda_runtime.h>
#include <cuda_bf16.h>
#include <math.h>
#include <stdint.h>

// ---------------- problem constants ----------------
#define D_MODEL 1024
#define D_FF    4096
#define NH      16
#define DKV     64
#define SEQ     2048
#define BATCH   2
#define ROWS    (BATCH*SEQ)        // 4096
#define RELN    (2*SEQ-1)          // 4095

// ---------------- scratch (device globals, no allocation) ----------------
__device__ float g_normed [ROWS*D_MODEL];
__device__ float g_q      [ROWS*D_MODEL];
__device__ float g_k      [ROWS*D_MODEL];
__device__ float g_v      [ROWS*D_MODEL];
__device__ float g_ctx    [ROWS*D_MODEL];
__device__ float g_hidden2[ROWS*D_MODEL];
__device__ float g_normed2[ROWS*D_MODEL];
__device__ float g_ff1    [ROWS*D_FF];
__device__ float g_ff2    [ROWS*D_FF];
__device__ float g_biasRel[NH*RELN];

// ---------------- T5 relative-position bias table ----------------
__global__ void bias_kernel(const float* __restrict__ rel_bias,
                            float* __restrict__ biasRel) {
    int idx = blockIdx.x * 256 + threadIdx.x;
    if (idx >= NH * RELN) return;
    int h   = idx / RELN;
    int r   = idx % RELN;
    int rel = r - (SEQ - 1);
    int ret = (rel > 0) ? 16 : 0;          // num_buckets/2
    int n   = rel < 0 ? -rel : rel;
    int v;
    if (n < 8) {                            // max_exact = 8
        v = n;
    } else {
        double t = log((double)n / 8.0) / log(16.0) * 8.0;
        v = 8 + (int)t;
        if (v > 15) v = 15;
    }
    biasRel[idx] = rel_bias[(ret + v) * NH + h];
}

// ---------------- RMSNorm ----------------
__global__ __launch_bounds__(256) void rmsnorm_kernel(
    const float* __restrict__ x, const float* __restrict__ w,
    float* __restrict__ out) {
    int row = blockIdx.x;
    int t   = threadIdx.x;
    const float4* xr = reinterpret_cast<const float4*>(x + (size_t)row * D_MODEL);
    float4 v = xr[t];
    float ss = v.x*v.x + v.y*v.y + v.z*v.z + v.w*v.w;
    #pragma unroll
    for (int o = 16; o > 0; o >>= 1) ss += __shfl_xor_sync(0xffffffffu, ss, o);
    __shared__ float ws[8];
    if ((t & 31) == 0) ws[t >> 5] = ss;
    __syncthreads();
    float tot = 0.f;
    #pragma unroll
    for (int i = 0; i < 8; i++) tot += ws[i];
    float r = rsqrtf(tot * (1.0f / D_MODEL) + 1e-6f);
    const float4* wr = reinterpret_cast<const float4*>(w);
    float4 wv = wr[t];
    float4 o4 = make_float4(v.x*r*wv.x, v.y*r*wv.y, v.z*r*wv.z, v.w*r*wv.w);
    reinterpret_cast<float4*>(out + (size_t)row * D_MODEL)[t] = o4;
}

// ============================================================================
// Tensor-core GEMM: C = A[MxK] @ B[KxN] (+Res), bf16x3 split for fp32 accuracy
// CTA 128x128, K-tile 32, 256 threads (8 warps of 64x32 warp tiles).
// A staged as [m][k] bf16 (row stride 40 elems = 80B -> conflict-free ldmatrix),
// B staged as [k][n] bf16 (row stride 136 elems = 272B), loaded with
// ldmatrix.trans to form col-major fragments.
// ============================================================================
#define APAD 40
#define BPAD 136

__device__ __forceinline__ void ldsm_x4(uint32_t* r, uint32_t addr) {
    asm volatile("ldmatrix.sync.aligned.m8n8.x4.shared.b16 {%0,%1,%2,%3},[%4];"
        : "=r"(r[0]), "=r"(r[1]), "=r"(r[2]), "=r"(r[3]) : "r"(addr));
}
__device__ __forceinline__ void ldsm_x2_t(uint32_t* r, uint32_t addr) {
    asm volatile("ldmatrix.sync.aligned.m8n8.x2.trans.shared.b16 {%0,%1},[%2];"
        : "=r"(r[0]), "=r"(r[1]) : "r"(addr));
}
__device__ __forceinline__ void mma_bf16(float* d, const uint32_t* a,
                                         const uint32_t* b) {
    asm volatile("mma.sync.aligned.m16n8k16.row.col.f32.bf16.bf16.f32 "
        "{%0,%1,%2,%3},{%4,%5,%6,%7},{%8,%9},{%0,%1,%2,%3};"
        : "+f"(d[0]), "+f"(d[1]), "+f"(d[2]), "+f"(d[3])
        : "r"(a[0]), "r"(a[1]), "r"(a[2]), "r"(a[3]), "r"(b[0]), "r"(b[1]));
}
__device__ __forceinline__ uint32_t pack2(__nv_bfloat16 lo, __nv_bfloat16 hi) {
    return ((uint32_t)__bfloat16_as_ushort(hi) << 16) |
           (uint32_t)__bfloat16_as_ushort(lo);
}

__global__ __launch_bounds__(256) void hgemm3_kernel(
    const float* __restrict__ A, const float* __restrict__ B,
    float* __restrict__ C, const float* __restrict__ Res,
    int M, int N, int K) {
    __shared__ __nv_bfloat16 Ah[128 * APAD];
    __shared__ __nv_bfloat16 Al[128 * APAD];
    __shared__ __nv_bfloat16 Bh[32 * BPAD];
    __shared__ __nv_bfloat16 Bl[32 * BPAD];

    int tid  = threadIdx.x;
    int lane = tid & 31;
    int wid  = tid >> 5;
    int wm   = wid & 1;    // 0..1  -> 64-row warp tile
    int wn   = wid >> 1;   // 0..3  -> 32-col warp tile
    int bx = blockIdx.x, by = blockIdx.y;

    // gmem loader mapping
    int ar = tid >> 3;          // 0..31  (A row, step 32)
    int af = (tid & 7) << 2;    // A float-col within 32-wide k tile
    int br = tid >> 5;          // 0..7   (B k-row, step 8)
    int bc = (tid & 31) << 2;   // B float-col within 128-wide n tile

    const float* Aptr = A + (size_t)(by * 128) * K;
    const float* Bptr = B + bx * 128;

    // smem shared-state addresses for ldmatrix
    uint32_t AhBase = (uint32_t)__cvta_generic_to_shared(Ah);
    uint32_t AlBase = (uint32_t)__cvta_generic_to_shared(Al);
    uint32_t BhBase = (uint32_t)__cvta_generic_to_shared(Bh);
    uint32_t BlBase = (uint32_t)__cvta_generic_to_shared(Bl);
    // A frag address (per m-tile, per k-step): row = wm*64+mt*16+(lane&15),
    // col = ks*16 + (lane>>4)*8   (bf16 elements, *2 bytes)
    int aRow  = wm * 64 + (lane & 15);
    int aColL = (lane >> 4) * 8;
    // B frag address: row k = ks*16+(lane&15), col = wn*32+nt*8
    int bRowL = (lane & 15);
    int bCol  = wn * 32;

    float acc[4][4][4];
    #pragma unroll
    for (int i = 0; i < 4; i++)
        #pragma unroll
        for (int j = 0; j < 4; j++)
            #pragma unroll
            for (int c = 0; c < 4; c++) acc[i][j][c] = 0.f;

    float4 areg[4], breg[4];
    // prefetch stage 0
    #pragma unroll
    for (int i = 0; i < 4; i++)
        areg[i] = *reinterpret_cast<const float4*>(Aptr + (size_t)(ar + 32 * i) * K + af);
    #pragma unroll
    for (int i = 0; i < 4; i++)
        breg[i] = *reinterpret_cast<const float4*>(Bptr + (size_t)(br + 8 * i) * N + bc);

    int nStages = K >> 5;
    for (int s = 0; s < nStages; s++) {
        __syncthreads();   // previous compute done before overwrite
        // convert + store A (hi/lo)
        #pragma unroll
        for (int i = 0; i < 4; i++) {
            const float* f = &areg[i].x;
            __nv_bfloat16 h[4], l[4];
            #pragma unroll
            for (int j = 0; j < 4; j++) {
                h[j] = __float2bfloat16_rn(f[j]);
                l[j] = __float2bfloat16_rn(f[j] - __bfloat162float(h[j]));
            }
            int off = (ar + 32 * i) * APAD + af;
            *reinterpret_cast<uint2*>(&Ah[off]) =
                make_uint2(pack2(h[0], h[1]), pack2(h[2], h[3]));
            *reinterpret_cast<uint2*>(&Al[off]) =
                make_uint2(pack2(l[0], l[1]), pack2(l[2], l[3]));
        }
        // convert + store B (hi/lo)
        #pragma unroll
        for (int i = 0; i < 4; i++) {
            const float* f = &breg[i].x;
            __nv_bfloat16 h[4], l[4];
            #pragma unroll
            for (int j = 0; j < 4; j++) {
                h[j] = __float2bfloat16_rn(f[j]);
                l[j] = __float2bfloat16_rn(f[j] - __bfloat162float(h[j]));
            }
            int off = (br + 8 * i) * BPAD + bc;
            *reinterpret_cast<uint2*>(&Bh[off]) =
                make_uint2(pack2(h[0], h[1]), pack2(h[2], h[3]));
            *reinterpret_cast<uint2*>(&Bl[off]) =
                make_uint2(pack2(l[0], l[1]), pack2(l[2], l[3]));
        }
        __syncthreads();

        // prefetch next stage while computing this one
        if (s + 1 < nStages) {
            int k0 = (s + 1) << 5;
            #pragma unroll
            for (int i = 0; i < 4; i++)
                areg[i] = *reinterpret_cast<const float4*>(
                    Aptr + (size_t)(ar + 32 * i) * K + k0 + af);
            #pragma unroll
            for (int i = 0; i < 4; i++)
                breg[i] = *reinterpret_cast<const float4*>(
                    Bptr + (size_t)(k0 + br + 8 * i) * N + bc);
        }

        #pragma unroll
        for (int ks = 0; ks < 2; ks++) {
            uint32_t afh[4][4], afl[4][4], bfh[4][2], bfl[4][2];
            #pragma unroll
            for (int mt = 0; mt < 4; mt++) {
                uint32_t off = (uint32_t)((aRow + mt * 16) * APAD +
                                          ks * 16 + aColL) * 2u;
                ldsm_x4(afh[mt], AhBase + off);
                ldsm_x4(afl[mt], AlBase + off);
            }
            #pragma unroll
            for (int nt = 0; nt < 4; nt++) {
                uint32_t off = (uint32_t)((ks * 16 + bRowL) * BPAD +
                                          bCol + nt * 8) * 2u;
                ldsm_x2_t(bfh[nt], BhBase + off);
                ldsm_x2_t(bfl[nt], BlBase + off);
            }
            #pragma unroll
            for (int mt = 0; mt < 4; mt++)
                #pragma unroll
                for (int nt = 0; nt < 4; nt++) {
                    mma_bf16(acc[mt][nt], afh[mt], bfh[nt]);
                    mma_bf16(acc[mt][nt], afh[mt], bfl[nt]);
                    mma_bf16(acc[mt][nt], afl[mt], bfh[nt]);
                }
        }
    }

    // epilogue: fragment c0,c1 = (row g, cols 2tg..2tg+1), c2,c3 = row g+8
    int g  = lane >> 2;
    int tg = lane & 3;
    #pragma unroll
    for (int mt = 0; mt < 4; mt++) {
        int row0 = by * 128 + wm * 64 + mt * 16 + g;
        #pragma unroll
        for (int nt = 0; nt < 4; nt++) {
            int col = bx * 128 + wn * 32 + nt * 8 + tg * 2;
            float* c0 = C + (size_t)row0 * N + col;
            float* c1 = C + (size_t)(row0 + 8) * N + col;
            float2 v0 = make_float2(acc[mt][nt][0], acc[mt][nt][1]);
            float2 v1 = make_float2(acc[mt][nt][2], acc[mt][nt][3]);
            if (Res) {
                const float2 r0 = *reinterpret_cast<const float2*>(
                    Res + (size_t)row0 * N + col);
                const float2 r1 = *reinterpret_cast<const float2*>(
                    Res + (size_t)(row0 + 8) * N + col);
                v0.x += r0.x; v0.y += r0.y;
                v1.x += r1.x; v1.y += r1.y;
            }
            *reinterpret_cast<float2*>(c0) = v0;
            *reinterpret_cast<float2*>(c1) = v1;
        }
    }
}

// ---------------- Flash attention (fp32, online softmax) ----------------
#define ATTN_SMEM_FLOATS (64*65 + 64*65 + 64*64 + 128 + 64)

__global__ __launch_bounds__(256) void attn_kernel(
    const float* __restrict__ q, const float* __restrict__ k,
    const float* __restrict__ v, const float* __restrict__ biasRel,
    const float* __restrict__ amask, float* __restrict__ ctx) {
    extern __shared__ float sm[];
    float* Qt    = sm;                    // [64][65]
    float* Kt    = Qt + 64 * 65;          // [64][65]; later P[m*65+c]
    float* Vs    = Kt + 64 * 65;          // [64][64]
    float* biasT = Vs + 64 * 64;
    float* maskT = biasT + 128;

    int tid = threadIdx.x;
    int tx = tid & 15, ty = tid >> 4;
    int qb = blockIdx.x << 6;
    int h  = blockIdx.y;
    int b  = blockIdx.z;

    const float* qg = q + (size_t)(b * SEQ) * D_MODEL + h * DKV;
    const float* kg = k + (size_t)(b * SEQ) * D_MODEL + h * DKV;
    const float* vg = v + (size_t)(b * SEQ) * D_MODEL + h * DKV;

    for (int it = tid; it < 1024; it += 256) {
        int m  = it >> 4;
        int d4 = (it & 15) << 2;
        float4 qv = *reinterpret_cast<const float4*>(
            qg + (size_t)(qb + m) * D_MODEL + d4);
        Qt[(d4 + 0) * 65 + m] = qv.x;
        Qt[(d4 + 1) * 65 + m] = qv.y;
        Qt[(d4 + 2) * 65 + m] = qv.z;
        Qt[(d4 + 3) * 65 + m] = qv.w;
    }

    float mI[4], lI[4], o[4][4];
    #pragma unroll
    for (int i = 0; i < 4; i++) {
        mI[i] = -1e30f; lI[i] = 0.f;
        #pragma unroll
        for (int j = 0; j < 4; j++) o[i][j] = 0.f;
    }

    int ty4 = ty * 4, tx4 = tx * 4;

    for (int jb = 0; jb < SEQ; jb += 64) {
        for (int it = tid; it < 1024; it += 256) {
            int c  = it >> 4;
            int d4 = (it & 15) << 2;
            float4 kv = *reinterpret_cast<const float4*>(
                kg + (size_t)(jb + c) * D_MODEL + d4);
            Kt[(d4 + 0) * 65 + c] = kv.x;
            Kt[(d4 + 1) * 65 + c] = kv.y;
            Kt[(d4 + 2) * 65 + c] = kv.z;
            Kt[(d4 + 3) * 65 + c] = kv.w;
            float4 vv = *reinterpret_cast<const float4*>(
                vg + (size_t)(jb + c) * D_MODEL + d4);
            *reinterpret_cast<float4*>(&Vs[c * 64 + d4]) = vv;
        }
        if (tid < 127)
            biasT[tid] = biasRel[h * RELN + (jb - qb + 1984 + tid)];
        if (tid >= 128 && tid < 192) {
            int c = tid - 128;
            maskT[c] = (1.0f - amask[b * SEQ + jb + c]) * -10000.0f;
        }
        __syncthreads();

        float sacc[4][4];
        #pragma unroll
        for (int i = 0; i < 4; i++)
            #pragma unroll
            for (int j = 0; j < 4; j++) sacc[i][j] = 0.f;
        #pragma unroll 8
        for (int d = 0; d < 64; d++) {
            float a0 = Qt[d * 65 + ty4 + 0];
            float a1 = Qt[d * 65 + ty4 + 1];
            float a2 = Qt[d * 65 + ty4 + 2];
            float a3 = Qt[d * 65 + ty4 + 3];
            float b0 = Kt[d * 65 + tx4 + 0];
            float b1 = Kt[d * 65 + tx4 + 1];
            float b2 = Kt[d * 65 + tx4 + 2];
            float b3 = Kt[d * 65 + tx4 + 3];
            sacc[0][0] = fmaf(a0,b0,sacc[0][0]); sacc[0][1] = fmaf(a0,b1,sacc[0][1]);
            sacc[0][2] = fmaf(a0,b2,sacc[0][2]); sacc[0][3] = fmaf(a0,b3,sacc[0][3]);
            sacc[1][0] = fmaf(a1,b0,sacc[1][0]); sacc[1][1] = fmaf(a1,b1,sacc[1][1]);
            sacc[1][2] = fmaf(a1,b2,sacc[1][2]); sacc[1][3] = fmaf(a1,b3,sacc[1][3]);
            sacc[2][0] = fmaf(a2,b0,sacc[2][0]); sacc[2][1] = fmaf(a2,b1,sacc[2][1]);
            sacc[2][2] = fmaf(a2,b2,sacc[2][2]); sacc[2][3] = fmaf(a2,b3,sacc[2][3]);
            sacc[3][0] = fmaf(a3,b0,sacc[3][0]); sacc[3][1] = fmaf(a3,b1,sacc[3][1]);
            sacc[3][2] = fmaf(a3,b2,sacc[3][2]); sacc[3][3] = fmaf(a3,b3,sacc[3][3]);
        }

        int bbase = tx4 - ty4 + 63;
        #pragma unroll
        for (int i = 0; i < 4; i++) {
            #pragma unroll
            for (int j = 0; j < 4; j++)
                sacc[i][j] += biasT[bbase + j - i] + maskT[tx4 + j];
            float rm = fmaxf(fmaxf(sacc[i][0], sacc[i][1]),
                             fmaxf(sacc[i][2], sacc[i][3]));
            #pragma unroll
            for (int off = 8; off > 0; off >>= 1)
                rm = fmaxf(rm, __shfl_xor_sync(0xffffffffu, rm, off));
            float mn = fmaxf(mI[i], rm);
            float alpha = expf(mI[i] - mn);
            float rs = 0.f;
            #pragma unroll
            for (int j = 0; j < 4; j++) {
                sacc[i][j] = expf(sacc[i][j] - mn);
                rs += sacc[i][j];
            }
            #pragma unroll
            for (int off = 8; off > 0; off >>= 1)
                rs += __shfl_xor_sync(0xffffffffu, rs, off);
            lI[i] = lI[i] * alpha + rs;
            mI[i] = mn;
            #pragma unroll
            for (int j = 0; j < 4; j++) o[i][j] *= alpha;
        }
        __syncthreads();

        float* Ps = Kt;
        #pragma unroll
        for (int i = 0; i < 4; i++)
            #pragma unroll
            for (int j = 0; j < 4; j++)
                Ps[(ty4 + i) * 65 + tx4 + j] = sacc[i][j];
        __syncthreads();

        #pragma unroll 4
        for (int c = 0; c < 64; c++) {
            float p0 = Ps[(ty4 + 0) * 65 + c];
            float p1 = Ps[(ty4 + 1) * 65 + c];
            float p2 = Ps[(ty4 + 2) * 65 + c];
            float p3 = Ps[(ty4 + 3) * 65 + c];
            float4 vv = *reinterpret_cast<const float4*>(&Vs[c * 64 + tx4]);
            o[0][0] = fmaf(p0,vv.x,o[0][0]); o[0][1] = fmaf(p0,vv.y,o[0][1]);
            o[0][2] = fmaf(p0,vv.z,o[0][2]); o[0][3] = fmaf(p0,vv.w,o[0][3]);
            o[1][0] = fmaf(p1,vv.x,o[1][0]); o[1][1] = fmaf(p1,vv.y,o[1][1]);
            o[1][2] = fmaf(p1,vv.z,o[1][2]); o[1][3] = fmaf(p1,vv.w,o[1][3]);
            o[2][0] = fmaf(p2,vv.x,o[2][0]); o[2][1] = fmaf(p2,vv.y,o[2][1]);
            o[2][2] = fmaf(p2,vv.z,o[2][2]); o[2][3] = fmaf(p2,vv.w,o[2][3]);
            o[3][0] = fmaf(p3,vv.x,o[3][0]); o[3][1] = fmaf(p3,vv.y,o[3][1]);
            o[3][2] = fmaf(p3,vv.z,o[3][2]); o[3][3] = fmaf(p3,vv.w,o[3][3]);
        }
        __syncthreads();
    }

    #pragma unroll
    for (int i = 0; i < 4; i++) {
        float inv = 1.0f / lI[i];
        int row = qb + ty4 + i;
        float4 ov = make_float4(o[i][0]*inv, o[i][1]*inv, o[i][2]*inv, o[i][3]*inv);
        *reinterpret_cast<float4*>(
            ctx + (size_t)(b * SEQ + row) * D_MODEL + h * DKV + tx4) = ov;
    }
}

// ---------------- gelu_new(ff1) * ff2 -> ff1 ----------------
__global__ void gelu_mul_kernel(float4* __restrict__ a,
                                const float4* __restrict__ bsrc, int n4) {
    int i = blockIdx.x * 256 + threadIdx.x;
    if (i >= n4) return;
    const float C = 0.7978845608028654f;
    float4 x = a[i];
    float4 g = bsrc[i];
    float4 r;
    r.x = 0.5f * x.x * (1.0f + tanhf(C * (x.x + 0.044715f * x.x * x.x * x.x))) * g.x;
    r.y = 0.5f * x.y * (1.0f + tanhf(C * (x.y + 0.044715f * x.y * x.y * x.y))) * g.y;
    r.z = 0.5f * x.z * (1.0f + tanhf(C * (x.z + 0.044715f * x.z * x.z * x.z))) * g.z;
    r.w = 0.5f * x.w * (1.0f + tanhf(C * (x.w + 0.044715f * x.w * x.w * x.w))) * g.w;
    a[i] = r;
}

// ---------------- launch ----------------
extern "C" void kernel_launch(void* const* d_in, const int* in_sizes, int n_in,
                              void* d_out, int out_size) {
    (void)in_sizes; (void)n_in; (void)out_size;
    const float* hidden = (const float*)d_in[0];
    const float* amask  = (const float*)d_in[1];
    const float* ln1    = (const float*)d_in[2];
    const float* wq     = (const float*)d_in[3];
    const float* wk     = (const float*)d_in[4];
    const float* wv     = (const float*)d_in[5];
    const float* relb   = (const float*)d_in[6];
    const float* wo     = (const float*)d_in[7];
    const float* ln2    = (const float*)d_in[8];
    const float* w1     = (const float*)d_in[9];
    const float* w2     = (const float*)d_in[10];
    const float* wout   = (const float*)d_in[11];
    float* out = (float*)d_out;

    float *normed, *qb, *kb, *vb, *ctx, *hidden2, *normed2, *ff1, *ff2, *biasRel;
    cudaGetSymbolAddress((void**)&normed,  g_normed);
    cudaGetSymbolAddress((void**)&qb,      g_q);
    cudaGetSymbolAddress((void**)&kb,      g_k);
    cudaGetSymbolAddress((void**)&vb,      g_v);
    cudaGetSymbolAddress((void**)&ctx,     g_ctx);
    cudaGetSymbolAddress((void**)&hidden2, g_hidden2);
    cudaGetSymbolAddress((void**)&normed2, g_normed2);
    cudaGetSymbolAddress((void**)&ff1,     g_ff1);
    cudaGetSymbolAddress((void**)&ff2,     g_ff2);
    cudaGetSymbolAddress((void**)&biasRel, g_biasRel);

    const int attn_smem = ATTN_SMEM_FLOATS * (int)sizeof(float);
    cudaFuncSetAttribute(attn_kernel,
                         cudaFuncAttributeMaxDynamicSharedMemorySize, attn_smem);

    // 0) relative-position bias table
    bias_kernel<<<(NH * RELN + 255) / 256, 256>>>(relb, biasRel);
    // 1) pre-LN 1
    rmsnorm_kernel<<<ROWS, 256>>>(hidden, ln1, normed);
    // 2) QKV projections (tensor cores)
    dim3 g1(D_MODEL / 128, ROWS / 128);
    hgemm3_kernel<<<g1, 256>>>(normed, wq, qb, nullptr, ROWS, D_MODEL, D_MODEL);
    hgemm3_kernel<<<g1, 256>>>(normed, wk, kb, nullptr, ROWS, D_MODEL, D_MODEL);
    hgemm3_kernel<<<g1, 256>>>(normed, wv, vb, nullptr, ROWS, D_MODEL, D_MODEL);
    // 3) attention
    dim3 ga(SEQ / 64, NH, BATCH);
    attn_kernel<<<ga, 256, attn_smem>>>(qb, kb, vb, biasRel, amask, ctx);
    // 4) output projection + residual
    hgemm3_kernel<<<g1, 256>>>(ctx, wo, hidden2, hidden, ROWS, D_MODEL, D_MODEL);
    // 5) pre-LN 2
    rmsnorm_kernel<<<ROWS, 256>>>(hidden2, ln2, normed2);
    // 6) gated FFN
    dim3 g2(D_FF / 128, ROWS / 128);
    hgemm3_kernel<<<g2, 256>>>(normed2, w1, ff1, nullptr, ROWS, D_FF, D_MODEL);
    hgemm3_kernel<<<g2, 256>>>(normed2, w2, ff2, nullptr, ROWS, D_FF, D_MODEL);
    int n4 = ROWS * D_FF / 4;
    gelu_mul_kernel<<<(n4 + 255) / 256, 256>>>((float4*)ff1, (const float4*)ff2, n4);
    // 7) FFN output projection + residual -> d_out
    hgemm3_kernel<<<g1, 256>>>(ff1, wout, out, hidden2, ROWS, D_MODEL, D_FF);
}

// round 8
// speedup vs baseline: 2.0399x; 1.2406x over previous
#include <cuda_runtime.h>
#include <cuda_bf16.h>
#include <math.h>
#include <stdint.h>

// ---------------- problem constants ----------------
#define D_MODEL 1024
#define D_FF    4096
#define NH      16
#define DKV     64
#define SEQ     2048
#define BATCH   2
#define ROWS    (BATCH*SEQ)        // 4096
#define RELN    (2*SEQ-1)          // 4095

// ---------------- scratch (device globals, no allocation) ----------------
__device__ float g_q      [ROWS*D_MODEL];
__device__ float g_k      [ROWS*D_MODEL];
__device__ float g_v      [ROWS*D_MODEL];
__device__ float g_hidden2[ROWS*D_MODEL];
__device__ float g_ff1    [ROWS*D_FF];
__device__ float g_ff2    [ROWS*D_FF];
__device__ float g_biasRel[NH*RELN];

// bf16 hi/lo split buffers (activations)
__device__ __nv_bfloat16 g_nh [ROWS*D_MODEL], g_nl [ROWS*D_MODEL];   // normed1
__device__ __nv_bfloat16 g_n2h[ROWS*D_MODEL], g_n2l[ROWS*D_MODEL];   // normed2
__device__ __nv_bfloat16 g_cxh[ROWS*D_MODEL], g_cxl[ROWS*D_MODEL];   // ctx
__device__ __nv_bfloat16 g_f1h[ROWS*D_FF],    g_f1l[ROWS*D_FF];      // gated ff
// bf16 hi/lo split buffers (weights)
__device__ __nv_bfloat16 g_wqh[D_MODEL*D_MODEL], g_wql[D_MODEL*D_MODEL];
__device__ __nv_bfloat16 g_wkh[D_MODEL*D_MODEL], g_wkl[D_MODEL*D_MODEL];
__device__ __nv_bfloat16 g_wvh[D_MODEL*D_MODEL], g_wvl[D_MODEL*D_MODEL];
__device__ __nv_bfloat16 g_woh[D_MODEL*D_MODEL], g_wol[D_MODEL*D_MODEL];
__device__ __nv_bfloat16 g_w1h[D_MODEL*D_FF],    g_w1l[D_MODEL*D_FF];
__device__ __nv_bfloat16 g_w2h[D_MODEL*D_FF],    g_w2l[D_MODEL*D_FF];
__device__ __nv_bfloat16 g_wouth[D_FF*D_MODEL],  g_woutl[D_FF*D_MODEL];

// ---------------- helpers ----------------
__device__ __forceinline__ uint32_t pack2(__nv_bfloat16 lo, __nv_bfloat16 hi) {
    return ((uint32_t)__bfloat16_as_ushort(hi) << 16) |
           (uint32_t)__bfloat16_as_ushort(lo);
}
__device__ __forceinline__ void split4(const float* f, uint2& vh, uint2& vl) {
    __nv_bfloat16 h[4], l[4];
    #pragma unroll
    for (int j = 0; j < 4; j++) {
        h[j] = __float2bfloat16_rn(f[j]);
        l[j] = __float2bfloat16_rn(f[j] - __bfloat162float(h[j]));
    }
    vh = make_uint2(pack2(h[0], h[1]), pack2(h[2], h[3]));
    vl = make_uint2(pack2(l[0], l[1]), pack2(l[2], l[3]));
}

// ---------------- T5 relative-position bias table ----------------
__global__ void bias_kernel(const float* __restrict__ rel_bias,
                            float* __restrict__ biasRel) {
    int idx = blockIdx.x * 256 + threadIdx.x;
    if (idx >= NH * RELN) return;
    int h   = idx / RELN;
    int r   = idx % RELN;
    int rel = r - (SEQ - 1);
    int ret = (rel > 0) ? 16 : 0;
    int n   = rel < 0 ? -rel : rel;
    int v;
    if (n < 8) {
        v = n;
    } else {
        double t = log((double)n / 8.0) / log(16.0) * 8.0;
        v = 8 + (int)t;
        if (v > 15) v = 15;
    }
    biasRel[idx] = rel_bias[(ret + v) * NH + h];
}

// ---------------- generic fp32 -> bf16 hi/lo split ----------------
__global__ void split_kernel(const float4* __restrict__ src,
                             uint2* __restrict__ dh, uint2* __restrict__ dl,
                             int n4) {
    int i = blockIdx.x * 256 + threadIdx.x;
    if (i >= n4) return;
    float4 v = src[i];
    uint2 vh, vl;
    split4(&v.x, vh, vl);
    dh[i] = vh; dl[i] = vl;
}

// ---------------- RMSNorm -> bf16 hi/lo ----------------
__global__ __launch_bounds__(256) void rmsnorm_split_kernel(
    const float* __restrict__ x, const float* __restrict__ w,
    uint2* __restrict__ oh, uint2* __restrict__ ol) {
    int row = blockIdx.x;
    int t   = threadIdx.x;
    const float4* xr = reinterpret_cast<const float4*>(x + (size_t)row * D_MODEL);
    float4 v = xr[t];
    float ss = v.x*v.x + v.y*v.y + v.z*v.z + v.w*v.w;
    #pragma unroll
    for (int o = 16; o > 0; o >>= 1) ss += __shfl_xor_sync(0xffffffffu, ss, o);
    __shared__ float ws[8];
    if ((t & 31) == 0) ws[t >> 5] = ss;
    __syncthreads();
    float tot = 0.f;
    #pragma unroll
    for (int i = 0; i < 8; i++) tot += ws[i];
    float r = rsqrtf(tot * (1.0f / D_MODEL) + 1e-6f);
    const float4* wr = reinterpret_cast<const float4*>(w);
    float4 wv = wr[t];
    float o4[4] = {v.x*r*wv.x, v.y*r*wv.y, v.z*r*wv.z, v.w*r*wv.w};
    uint2 vh, vl;
    split4(o4, vh, vl);
    oh[(size_t)row * (D_MODEL/4) + t] = vh;
    ol[(size_t)row * (D_MODEL/4) + t] = vl;
}

// ============================================================================
// Tensor-core GEMM on pre-split bf16: C = A @ B (+Res), fp32 accuracy via
// bf16x3 (Ah·Bh + Ah·Bl + Al·Bh). CTA 128x128, k-tile 32, cp.async double
// buffer, 256 threads, 8 warps of 64x32.
// ============================================================================
#define APAD 40     // elements; row stride 80B (16B-aligned)
#define BPAD 136    // elements; row stride 272B (16B-aligned)
#define ASTG (128*APAD)
#define BSTG (32*BPAD)
#define STG_ELEMS (2*ASTG + 2*BSTG)
#define STG_BYTES (STG_ELEMS*2)
#define GEMM_SMEM (2*STG_BYTES)

__device__ __forceinline__ void ldsm_x4(uint32_t* r, uint32_t addr) {
    asm volatile("ldmatrix.sync.aligned.m8n8.x4.shared.b16 {%0,%1,%2,%3},[%4];"
        : "=r"(r[0]), "=r"(r[1]), "=r"(r[2]), "=r"(r[3]) : "r"(addr));
}
__device__ __forceinline__ void ldsm_x2_t(uint32_t* r, uint32_t addr) {
    asm volatile("ldmatrix.sync.aligned.m8n8.x2.trans.shared.b16 {%0,%1},[%2];"
        : "=r"(r[0]), "=r"(r[1]) : "r"(addr));
}
__device__ __forceinline__ void mma_bf16(float* d, const uint32_t* a,
                                         const uint32_t* b) {
    asm volatile("mma.sync.aligned.m16n8k16.row.col.f32.bf16.bf16.f32 "
        "{%0,%1,%2,%3},{%4,%5,%6,%7},{%8,%9},{%0,%1,%2,%3};"
        : "+f"(d[0]), "+f"(d[1]), "+f"(d[2]), "+f"(d[3])
        : "r"(a[0]), "r"(a[1]), "r"(a[2]), "r"(a[3]), "r"(b[0]), "r"(b[1]));
}
__device__ __forceinline__ void cp16(uint32_t dst, const void* src) {
    asm volatile("cp.async.cg.shared.global [%0], [%1], 16;"
        :: "r"(dst), "l"(src));
}
__device__ __forceinline__ void cp_commit() {
    asm volatile("cp.async.commit_group;");
}
template <int N>
__device__ __forceinline__ void cp_wait() {
    asm volatile("cp.async.wait_group %0;" :: "n"(N));
}

__global__ __launch_bounds__(256) void bgemm_kernel(
    const __nv_bfloat16* __restrict__ Ah, const __nv_bfloat16* __restrict__ Al,
    const __nv_bfloat16* __restrict__ Bh, const __nv_bfloat16* __restrict__ Bl,
    float* __restrict__ C, const float* __restrict__ Res,
    int M, int N, int K) {
    extern __shared__ __nv_bfloat16 smem[];
    uint32_t sbase = (uint32_t)__cvta_generic_to_shared(smem);

    int tid  = threadIdx.x;
    int lane = tid & 31;
    int wid  = tid >> 5;
    int wm   = wid & 1;
    int wn   = wid >> 1;
    int bx = blockIdx.x, by = blockIdx.y;

    const __nv_bfloat16* AhB = Ah + (size_t)(by * 128) * K;
    const __nv_bfloat16* AlB = Al + (size_t)(by * 128) * K;
    const __nv_bfloat16* BhB = Bh + bx * 128;
    const __nv_bfloat16* BlB = Bl + bx * 128;

    // loader mapping (each thread: 2 chunks of A, 2 of B, x hi/lo)
    int ar0 = tid >> 2;               // A rows for chunks: tid>>2, +64
    int ac8 = (tid & 3) * 8;          // elem col within 32-wide k
    int bk0 = tid >> 4;               // B k-rows: tid>>4, +16
    int bc8 = (tid & 15) * 8;

    // ldmatrix fragment addressing (element offsets within a stage region)
    int aRow  = wm * 64 + (lane & 15);
    int aColL = (lane >> 4) * 8;
    int bRowL = (lane & 15);
    int bCol  = wn * 32;

    float acc[4][4][4];
    #pragma unroll
    for (int i = 0; i < 4; i++)
        #pragma unroll
        for (int j = 0; j < 4; j++)
            #pragma unroll
            for (int c = 0; c < 4; c++) acc[i][j][c] = 0.f;

    int nS = K >> 5;

    // ---- issue loads for one stage ----
    auto issue = [&](int buf, int k0) {
        uint32_t sb = sbase + buf * STG_BYTES;
        #pragma unroll
        for (int i = 0; i < 2; i++) {
            int r = ar0 + i * 64;
            size_t goff = (size_t)r * K + k0 + ac8;
            uint32_t soff = (uint32_t)(r * APAD + ac8) * 2u;
            cp16(sb + soff,               AhB + goff);
            cp16(sb + ASTG * 2 + soff,    AlB + goff);
        }
        #pragma unroll
        for (int i = 0; i < 2; i++) {
            int kr = bk0 + i * 16;
            size_t goff = (size_t)(k0 + kr) * N + bc8;
            uint32_t soff = (uint32_t)(kr * BPAD + bc8) * 2u;
            cp16(sb + 2 * ASTG * 2 + soff,              BhB + goff);
            cp16(sb + 2 * ASTG * 2 + BSTG * 2 + soff,   BlB + goff);
        }
        cp_commit();
    };

    issue(0, 0);

    for (int s = 0; s < nS; s++) {
        if (s + 1 < nS) {
            issue((s + 1) & 1, (s + 1) << 5);
            cp_wait<1>();
        } else {
            cp_wait<0>();
        }
        __syncthreads();

        uint32_t sb  = sbase + (s & 1) * STG_BYTES;
        uint32_t sbAl = sb + ASTG * 2;
        uint32_t sbBh = sb + 2 * ASTG * 2;
        uint32_t sbBl = sbBh + BSTG * 2;

        #pragma unroll
        for (int ks = 0; ks < 2; ks++) {
            uint32_t afh[4][4], afl[4][4], bfh[4][2], bfl[4][2];
            #pragma unroll
            for (int mt = 0; mt < 4; mt++) {
                uint32_t off = (uint32_t)((aRow + mt * 16) * APAD +
                                          ks * 16 + aColL) * 2u;
                ldsm_x4(afh[mt], sb + off);
                ldsm_x4(afl[mt], sbAl + off);
            }
            #pragma unroll
            for (int nt = 0; nt < 4; nt++) {
                uint32_t off = (uint32_t)((ks * 16 + bRowL) * BPAD +
                                          bCol + nt * 8) * 2u;
                ldsm_x2_t(bfh[nt], sbBh + off);
                ldsm_x2_t(bfl[nt], sbBl + off);
            }
            #pragma unroll
            for (int mt = 0; mt < 4; mt++)
                #pragma unroll
                for (int nt = 0; nt < 4; nt++) {
                    mma_bf16(acc[mt][nt], afh[mt], bfh[nt]);
                    mma_bf16(acc[mt][nt], afh[mt], bfl[nt]);
                    mma_bf16(acc[mt][nt], afl[mt], bfh[nt]);
                }
        }
        __syncthreads();
    }

    // epilogue
    int g  = lane >> 2;
    int tg = lane & 3;
    #pragma unroll
    for (int mt = 0; mt < 4; mt++) {
        int row0 = by * 128 + wm * 64 + mt * 16 + g;
        #pragma unroll
        for (int nt = 0; nt < 4; nt++) {
            int col = bx * 128 + wn * 32 + nt * 8 + tg * 2;
            float* c0 = C + (size_t)row0 * N + col;
            float* c1 = C + (size_t)(row0 + 8) * N + col;
            float2 v0 = make_float2(acc[mt][nt][0], acc[mt][nt][1]);
            float2 v1 = make_float2(acc[mt][nt][2], acc[mt][nt][3]);
            if (Res) {
                const float2 r0 = *reinterpret_cast<const float2*>(
                    Res + (size_t)row0 * N + col);
                const float2 r1 = *reinterpret_cast<const float2*>(
                    Res + (size_t)(row0 + 8) * N + col);
                v0.x += r0.x; v0.y += r0.y;
                v1.x += r1.x; v1.y += r1.y;
            }
            *reinterpret_cast<float2*>(c0) = v0;
            *reinterpret_cast<float2*>(c1) = v1;
        }
    }
}

// ---------------- Flash attention (fp32, online softmax) ----------------
// writes ctx as bf16 hi/lo directly
#define ATTN_SMEM_FLOATS (64*65 + 64*65 + 64*64 + 128 + 64)

__global__ __launch_bounds__(256) void attn_kernel(
    const float* __restrict__ q, const float* __restrict__ k,
    const float* __restrict__ v, const float* __restrict__ biasRel,
    const float* __restrict__ amask,
    __nv_bfloat16* __restrict__ ctxh, __nv_bfloat16* __restrict__ ctxl) {
    extern __shared__ float sm[];
    float* Qt    = sm;                    // [64][65]
    float* Kt    = Qt + 64 * 65;          // [64][65]; later P[m*65+c]
    float* Vs    = Kt + 64 * 65;          // [64][64]
    float* biasT = Vs + 64 * 64;
    float* maskT = biasT + 128;

    int tid = threadIdx.x;
    int tx = tid & 15, ty = tid >> 4;
    int qb = blockIdx.x << 6;
    int h  = blockIdx.y;
    int b  = blockIdx.z;

    const float* qg = q + (size_t)(b * SEQ) * D_MODEL + h * DKV;
    const float* kg = k + (size_t)(b * SEQ) * D_MODEL + h * DKV;
    const float* vg = v + (size_t)(b * SEQ) * D_MODEL + h * DKV;

    for (int it = tid; it < 1024; it += 256) {
        int m  = it >> 4;
        int d4 = (it & 15) << 2;
        float4 qv = *reinterpret_cast<const float4*>(
            qg + (size_t)(qb + m) * D_MODEL + d4);
        Qt[(d4 + 0) * 65 + m] = qv.x;
        Qt[(d4 + 1) * 65 + m] = qv.y;
        Qt[(d4 + 2) * 65 + m] = qv.z;
        Qt[(d4 + 3) * 65 + m] = qv.w;
    }

    float mI[4], lI[4], o[4][4];
    #pragma unroll
    for (int i = 0; i < 4; i++) {
        mI[i] = -1e30f; lI[i] = 0.f;
        #pragma unroll
        for (int j = 0; j < 4; j++) o[i][j] = 0.f;
    }

    int ty4 = ty * 4, tx4 = tx * 4;

    for (int jb = 0; jb < SEQ; jb += 64) {
        for (int it = tid; it < 1024; it += 256) {
            int c  = it >> 4;
            int d4 = (it & 15) << 2;
            float4 kv = *reinterpret_cast<const float4*>(
                kg + (size_t)(jb + c) * D_MODEL + d4);
            Kt[(d4 + 0) * 65 + c] = kv.x;
            Kt[(d4 + 1) * 65 + c] = kv.y;
            Kt[(d4 + 2) * 65 + c] = kv.z;
            Kt[(d4 + 3) * 65 + c] = kv.w;
            float4 vv = *reinterpret_cast<const float4*>(
                vg + (size_t)(jb + c) * D_MODEL + d4);
            *reinterpret_cast<float4*>(&Vs[c * 64 + d4]) = vv;
        }
        if (tid < 127)
            biasT[tid] = biasRel[h * RELN + (jb - qb + 1984 + tid)];
        if (tid >= 128 && tid < 192) {
            int c = tid - 128;
            maskT[c] = (1.0f - amask[b * SEQ + jb + c]) * -10000.0f;
        }
        __syncthreads();

        float sacc[4][4];
        #pragma unroll
        for (int i = 0; i < 4; i++)
            #pragma unroll
            for (int j = 0; j < 4; j++) sacc[i][j] = 0.f;
        #pragma unroll 8
        for (int d = 0; d < 64; d++) {
            float a0 = Qt[d * 65 + ty4 + 0];
            float a1 = Qt[d * 65 + ty4 + 1];
            float a2 = Qt[d * 65 + ty4 + 2];
            float a3 = Qt[d * 65 + ty4 + 3];
            float b0 = Kt[d * 65 + tx4 + 0];
            float b1 = Kt[d * 65 + tx4 + 1];
            float b2 = Kt[d * 65 + tx4 + 2];
            float b3 = Kt[d * 65 + tx4 + 3];
            sacc[0][0] = fmaf(a0,b0,sacc[0][0]); sacc[0][1] = fmaf(a0,b1,sacc[0][1]);
            sacc[0][2] = fmaf(a0,b2,sacc[0][2]); sacc[0][3] = fmaf(a0,b3,sacc[0][3]);
            sacc[1][0] = fmaf(a1,b0,sacc[1][0]); sacc[1][1] = fmaf(a1,b1,sacc[1][1]);
            sacc[1][2] = fmaf(a1,b2,sacc[1][2]); sacc[1][3] = fmaf(a1,b3,sacc[1][3]);
            sacc[2][0] = fmaf(a2,b0,sacc[2][0]); sacc[2][1] = fmaf(a2,b1,sacc[2][1]);
            sacc[2][2] = fmaf(a2,b2,sacc[2][2]); sacc[2][3] = fmaf(a2,b3,sacc[2][3]);
            sacc[3][0] = fmaf(a3,b0,sacc[3][0]); sacc[3][1] = fmaf(a3,b1,sacc[3][1]);
            sacc[3][2] = fmaf(a3,b2,sacc[3][2]); sacc[3][3] = fmaf(a3,b3,sacc[3][3]);
        }

        int bbase = tx4 - ty4 + 63;
        #pragma unroll
        for (int i = 0; i < 4; i++) {
            #pragma unroll
            for (int j = 0; j < 4; j++)
                sacc[i][j] += biasT[bbase + j - i] + maskT[tx4 + j];
            float rm = fmaxf(fmaxf(sacc[i][0], sacc[i][1]),
                             fmaxf(sacc[i][2], sacc[i][3]));
            #pragma unroll
            for (int off = 8; off > 0; off >>= 1)
                rm = fmaxf(rm, __shfl_xor_sync(0xffffffffu, rm, off));
            float mn = fmaxf(mI[i], rm);
            float alpha = expf(mI[i] - mn);
            float rs = 0.f;
            #pragma unroll
            for (int j = 0; j < 4; j++) {
                sacc[i][j] = expf(sacc[i][j] - mn);
                rs += sacc[i][j];
            }
            #pragma unroll
            for (int off = 8; off > 0; off >>= 1)
                rs += __shfl_xor_sync(0xffffffffu, rs, off);
            lI[i] = lI[i] * alpha + rs;
            mI[i] = mn;
            #pragma unroll
            for (int j = 0; j < 4; j++) o[i][j] *= alpha;
        }
        __syncthreads();

        float* Ps = Kt;
        #pragma unroll
        for (int i = 0; i < 4; i++)
            #pragma unroll
            for (int j = 0; j < 4; j++)
                Ps[(ty4 + i) * 65 + tx4 + j] = sacc[i][j];
        __syncthreads();

        #pragma unroll 4
        for (int c = 0; c < 64; c++) {
            float p0 = Ps[(ty4 + 0) * 65 + c];
            float p1 = Ps[(ty4 + 1) * 65 + c];
            float p2 = Ps[(ty4 + 2) * 65 + c];
            float p3 = Ps[(ty4 + 3) * 65 + c];
            float4 vv = *reinterpret_cast<const float4*>(&Vs[c * 64 + tx4]);
            o[0][0] = fmaf(p0,vv.x,o[0][0]); o[0][1] = fmaf(p0,vv.y,o[0][1]);
            o[0][2] = fmaf(p0,vv.z,o[0][2]); o[0][3] = fmaf(p0,vv.w,o[0][3]);
            o[1][0] = fmaf(p1,vv.x,o[1][0]); o[1][1] = fmaf(p1,vv.y,o[1][1]);
            o[1][2] = fmaf(p1,vv.z,o[1][2]); o[1][3] = fmaf(p1,vv.w,o[1][3]);
            o[2][0] = fmaf(p2,vv.x,o[2][0]); o[2][1] = fmaf(p2,vv.y,o[2][1]);
            o[2][2] = fmaf(p2,vv.z,o[2][2]); o[2][3] = fmaf(p2,vv.w,o[2][3]);
            o[3][0] = fmaf(p3,vv.x,o[3][0]); o[3][1] = fmaf(p3,vv.y,o[3][1]);
            o[3][2] = fmaf(p3,vv.z,o[3][2]); o[3][3] = fmaf(p3,vv.w,o[3][3]);
        }
        __syncthreads();
    }

    #pragma unroll
    for (int i = 0; i < 4; i++) {
        float inv = 1.0f / lI[i];
        int row = qb + ty4 + i;
        float ov[4] = {o[i][0]*inv, o[i][1]*inv, o[i][2]*inv, o[i][3]*inv};
        uint2 vh, vl;
        split4(ov, vh, vl);
        size_t off = (size_t)(b * SEQ + row) * D_MODEL + h * DKV + tx4;
        *reinterpret_cast<uint2*>(ctxh + off) = vh;
        *reinterpret_cast<uint2*>(ctxl + off) = vl;
    }
}

// ---------------- gelu_new(ff1) * ff2 -> bf16 hi/lo ----------------
__global__ void gelu_split_kernel(const float4* __restrict__ a,
                                  const float4* __restrict__ bsrc,
                                  uint2* __restrict__ dh,
                                  uint2* __restrict__ dl, int n4) {
    int i = blockIdx.x * 256 + threadIdx.x;
    if (i >= n4) return;
    const float C = 0.7978845608028654f;
    float4 x = a[i];
    float4 g = bsrc[i];
    float r[4];
    r[0] = 0.5f * x.x * (1.0f + tanhf(C * (x.x + 0.044715f * x.x * x.x * x.x))) * g.x;
    r[1] = 0.5f * x.y * (1.0f + tanhf(C * (x.y + 0.044715f * x.y * x.y * x.y))) * g.y;
    r[2] = 0.5f * x.z * (1.0f + tanhf(C * (x.z + 0.044715f * x.z * x.z * x.z))) * g.z;
    r[3] = 0.5f * x.w * (1.0f + tanhf(C * (x.w + 0.044715f * x.w * x.w * x.w))) * g.w;
    uint2 vh, vl;
    split4(r, vh, vl);
    dh[i] = vh; dl[i] = vl;
}

// ---------------- launch ----------------
extern "C" void kernel_launch(void* const* d_in, const int* in_sizes, int n_in,
                              void* d_out, int out_size) {
    (void)in_sizes; (void)n_in; (void)out_size;
    const float* hidden = (const float*)d_in[0];
    const float* amask  = (const float*)d_in[1];
    const float* ln1    = (const float*)d_in[2];
    const float* wq     = (const float*)d_in[3];
    const float* wk     = (const float*)d_in[4];
    const float* wv     = (const float*)d_in[5];
    const float* relb   = (const float*)d_in[6];
    const float* wo     = (const float*)d_in[7];
    const float* ln2    = (const float*)d_in[8];
    const float* w1     = (const float*)d_in[9];
    const float* w2     = (const float*)d_in[10];
    const float* wout   = (const float*)d_in[11];
    float* out = (float*)d_out;

    float *qb, *kb, *vb, *hidden2, *ff1, *ff2, *biasRel;
    cudaGetSymbolAddress((void**)&qb,      g_q);
    cudaGetSymbolAddress((void**)&kb,      g_k);
    cudaGetSymbolAddress((void**)&vb,      g_v);
    cudaGetSymbolAddress((void**)&hidden2, g_hidden2);
    cudaGetSymbolAddress((void**)&ff1,     g_ff1);
    cudaGetSymbolAddress((void**)&ff2,     g_ff2);
    cudaGetSymbolAddress((void**)&biasRel, g_biasRel);

    __nv_bfloat16 *nh,*nl,*n2h,*n2l,*cxh,*cxl,*f1h,*f1l;
    __nv_bfloat16 *wqh,*wql,*wkh,*wkl,*wvh,*wvl,*woh,*wol;
    __nv_bfloat16 *w1h,*w1l,*w2h,*w2l,*wouth,*woutl;
    cudaGetSymbolAddress((void**)&nh,  g_nh);   cudaGetSymbolAddress((void**)&nl,  g_nl);
    cudaGetSymbolAddress((void**)&n2h, g_n2h);  cudaGetSymbolAddress((void**)&n2l, g_n2l);
    cudaGetSymbolAddress((void**)&cxh, g_cxh);  cudaGetSymbolAddress((void**)&cxl, g_cxl);
    cudaGetSymbolAddress((void**)&f1h, g_f1h);  cudaGetSymbolAddress((void**)&f1l, g_f1l);
    cudaGetSymbolAddress((void**)&wqh, g_wqh);  cudaGetSymbolAddress((void**)&wql, g_wql);
    cudaGetSymbolAddress((void**)&wkh, g_wkh);  cudaGetSymbolAddress((void**)&wkl, g_wkl);
    cudaGetSymbolAddress((void**)&wvh, g_wvh);  cudaGetSymbolAddress((void**)&wvl, g_wvl);
    cudaGetSymbolAddress((void**)&woh, g_woh);  cudaGetSymbolAddress((void**)&wol, g_wol);
    cudaGetSymbolAddress((void**)&w1h, g_w1h);  cudaGetSymbolAddress((void**)&w1l, g_w1l);
    cudaGetSymbolAddress((void**)&w2h, g_w2h);  cudaGetSymbolAddress((void**)&w2l, g_w2l);
    cudaGetSymbolAddress((void**)&wouth, g_wouth); cudaGetSymbolAddress((void**)&woutl, g_woutl);

    const int attn_smem = ATTN_SMEM_FLOATS * (int)sizeof(float);
    cudaFuncSetAttribute(attn_kernel,
                         cudaFuncAttributeMaxDynamicSharedMemorySize, attn_smem);
    cudaFuncSetAttribute(bgemm_kernel,
                         cudaFuncAttributeMaxDynamicSharedMemorySize, GEMM_SMEM);

    const int nDM = D_MODEL * D_MODEL / 4;   // 262144 float4s
    const int nDF = D_MODEL * D_FF / 4;      // 1048576

    // 0) bias table + weight splits
    bias_kernel<<<(NH * RELN + 255) / 256, 256>>>(relb, biasRel);
    split_kernel<<<nDM / 256, 256>>>((const float4*)wq, (uint2*)wqh, (uint2*)wql, nDM);
    split_kernel<<<nDM / 256, 256>>>((const float4*)wk, (uint2*)wkh, (uint2*)wkl, nDM);
    split_kernel<<<nDM / 256, 256>>>((const float4*)wv, (uint2*)wvh, (uint2*)wvl, nDM);
    split_kernel<<<nDM / 256, 256>>>((const float4*)wo, (uint2*)woh, (uint2*)wol, nDM);
    split_kernel<<<nDF / 256, 256>>>((const float4*)w1, (uint2*)w1h, (uint2*)w1l, nDF);
    split_kernel<<<nDF / 256, 256>>>((const float4*)w2, (uint2*)w2h, (uint2*)w2l, nDF);
    split_kernel<<<nDF / 256, 256>>>((const float4*)wout, (uint2*)wouth, (uint2*)woutl, nDF);

    // 1) pre-LN 1 -> bf16 hi/lo
    rmsnorm_split_kernel<<<ROWS, 256>>>(hidden, ln1, (uint2*)nh, (uint2*)nl);

    // 2) QKV projections (tensor cores)
    dim3 g1(D_MODEL / 128, ROWS / 128);
    bgemm_kernel<<<g1, 256, GEMM_SMEM>>>(nh, nl, wqh, wql, qb, nullptr,
                                         ROWS, D_MODEL, D_MODEL);
    bgemm_kernel<<<g1, 256, GEMM_SMEM>>>(nh, nl, wkh, wkl, kb, nullptr,
                                         ROWS, D_MODEL, D_MODEL);
    bgemm_kernel<<<g1, 256, GEMM_SMEM>>>(nh, nl, wvh, wvl, vb, nullptr,
                                         ROWS, D_MODEL, D_MODEL);
    // 3) attention -> ctx hi/lo
    dim3 ga(SEQ / 64, NH, BATCH);
    attn_kernel<<<ga, 256, attn_smem>>>(qb, kb, vb, biasRel, amask, cxh, cxl);
    // 4) output projection + residual
    bgemm_kernel<<<g1, 256, GEMM_SMEM>>>(cxh, cxl, woh, wol, hidden2, hidden,
                                         ROWS, D_MODEL, D_MODEL);
    // 5) pre-LN 2 -> bf16 hi/lo
    rmsnorm_split_kernel<<<ROWS, 256>>>(hidden2, ln2, (uint2*)n2h, (uint2*)n2l);
    // 6) gated FFN
    dim3 g2(D_FF / 128, ROWS / 128);
    bgemm_kernel<<<g2, 256, GEMM_SMEM>>>(n2h, n2l, w1h, w1l, ff1, nullptr,
                                         ROWS, D_FF, D_MODEL);
    bgemm_kernel<<<g2, 256, GEMM_SMEM>>>(n2h, n2l, w2h, w2l, ff2, nullptr,
                                         ROWS, D_FF, D_MODEL);
    int n4 = ROWS * D_FF / 4;
    gelu_split_kernel<<<(n4 + 255) / 256, 256>>>((const float4*)ff1,
                                                 (const float4*)ff2,
                                                 (uint2*)f1h, (uint2*)f1l, n4);
    // 7) FFN output projection + residual -> d_out
    bgemm_kernel<<<g1, 256, GEMM_SMEM>>>(f1h, f1l, wouth, woutl, out, hidden2,
                                         ROWS, D_MODEL, D_FF);
}